// round 1
// baseline (speedup 1.0000x reference)
#include <cuda_runtime.h>
#include <cuda_bf16.h>
#include <cstdint>

#define N_NODES   50000
#define DEG       16
#define IN_F      256
#define OUT_C     256   // NUM_HEADS * OUT_FEATS
#define NUM_HEADS 4
#define OUT_F     64
#define NEG_SLOPE 0.2f

// Scratch: projected features h = feat @ W, [N, 256] fp32 (51.2 MB, fits in L2)
__device__ float g_h[(size_t)N_NODES * OUT_C];

// ---------------------------------------------------------------------------
// Kernel 1: tiled fp32 GEMM  h[M,256] = feat[M,256] @ W[256,256]
// BM=64, BN=64, BK=16, 256 threads, 4x4 micro-tile per thread.
// ---------------------------------------------------------------------------
__global__ __launch_bounds__(256) void gat_gemm_kernel(
    const float* __restrict__ A,   // feat [M,256]
    const float* __restrict__ B,   // W    [256,256]
    float* __restrict__ C,         // g_h  [M,256]
    int M)
{
    __shared__ float As[16][65];   // padded: avoid 16-way bank conflict on store
    __shared__ float Bs[16][64];

    const int bm  = blockIdx.x * 64;
    const int bn  = blockIdx.y * 64;
    const int tid = threadIdx.x;
    const int tr  = tid >> 4;      // 0..15
    const int tc  = tid & 15;      // 0..15

    float acc[4][4];
    #pragma unroll
    for (int i = 0; i < 4; i++)
        #pragma unroll
        for (int j = 0; j < 4; j++) acc[i][j] = 0.f;

    for (int k0 = 0; k0 < IN_F; k0 += 16) {
        // Load A tile 64x16
        #pragma unroll
        for (int i = 0; i < 4; i++) {
            int idx = tid + i * 256;
            int r  = idx >> 4;
            int kk = idx & 15;
            int gr = bm + r;
            As[kk][r] = (gr < M) ? A[(size_t)gr * IN_F + k0 + kk] : 0.f;
        }
        // Load B tile 16x64
        #pragma unroll
        for (int i = 0; i < 4; i++) {
            int idx = tid + i * 256;
            int kk = idx >> 6;
            int c  = idx & 63;
            Bs[kk][c] = B[(size_t)(k0 + kk) * OUT_C + bn + c];
        }
        __syncthreads();

        #pragma unroll
        for (int kk = 0; kk < 16; kk++) {
            float a[4], b[4];
            #pragma unroll
            for (int i = 0; i < 4; i++) a[i] = As[kk][tr * 4 + i];
            #pragma unroll
            for (int j = 0; j < 4; j++) b[j] = Bs[kk][tc * 4 + j];
            #pragma unroll
            for (int i = 0; i < 4; i++)
                #pragma unroll
                for (int j = 0; j < 4; j++)
                    acc[i][j] += a[i] * b[j];
        }
        __syncthreads();
    }

    #pragma unroll
    for (int i = 0; i < 4; i++) {
        int gr = bm + tr * 4 + i;
        if (gr < M) {
            #pragma unroll
            for (int j = 0; j < 4; j++)
                C[(size_t)gr * OUT_C + bn + tc * 4 + j] = acc[i][j];
        }
    }
}

// ---------------------------------------------------------------------------
// Kernel 2: fused attention-score + segment-softmax + weighted aggregation.
// One block (256 threads) per destination node. DEG=16 edges, contiguous.
//   sh[0..15] : gathered src rows of h   (16 x 256 f32)
//   sh[16]    : dst row of h
// Per-warp score reductions -> per-head softmax over 16 -> weighted sum.
// ---------------------------------------------------------------------------
__global__ __launch_bounds__(256) void gat_agg_kernel(
    const int*   __restrict__ col_ind,
    const float* __restrict__ attn_l,   // [256] flat (H,F)
    const float* __restrict__ attn_r,   // [256]
    float*       __restrict__ out)      // [N,256]
{
    const int n    = blockIdx.x;
    const int tid  = threadIdx.x;
    const int warp = tid >> 5;
    const int lane = tid & 31;

    __shared__ float sh[17][256];
    __shared__ int   ssrc[16];
    __shared__ float colscore[16][4];
    __shared__ float rowscore[4];
    __shared__ float alpha[16][4];

    if (tid < 16) ssrc[tid] = col_ind[n * DEG + tid];
    __syncthreads();

    // Gather 16 src rows + dst row (coalesced 1KB row reads; h resident in L2)
    #pragma unroll
    for (int k = 0; k < 16; k++)
        sh[k][tid] = g_h[(size_t)ssrc[k] * OUT_C + tid];
    sh[16][tid] = g_h[(size_t)n * OUT_C + tid];
    __syncthreads();

    // Per-warp src-score reduction: warp w handles k = w and k = w+8.
    // Lane l sums c = l + 32q; q/2 selects the head (64 contiguous feats/head).
    #pragma unroll
    for (int kk = 0; kk < 2; kk++) {
        int k = warp + kk * 8;
        float ph[4] = {0.f, 0.f, 0.f, 0.f};
        #pragma unroll
        for (int q = 0; q < 8; q++) {
            int c = lane + q * 32;
            ph[q >> 1] += attn_r[c] * sh[k][c];
        }
        #pragma unroll
        for (int hd = 0; hd < 4; hd++) {
            float v = ph[hd];
            #pragma unroll
            for (int off = 16; off > 0; off >>= 1)
                v += __shfl_xor_sync(0xffffffff, v, off);
            if (lane == 0) colscore[k][hd] = v;
        }
    }
    // Warp 0 additionally reduces the dst row against attn_l.
    if (warp == 0) {
        float ph[4] = {0.f, 0.f, 0.f, 0.f};
        #pragma unroll
        for (int q = 0; q < 8; q++) {
            int c = lane + q * 32;
            ph[q >> 1] += attn_l[c] * sh[16][c];
        }
        #pragma unroll
        for (int hd = 0; hd < 4; hd++) {
            float v = ph[hd];
            #pragma unroll
            for (int off = 16; off > 0; off >>= 1)
                v += __shfl_xor_sync(0xffffffff, v, off);
            if (lane == 0) rowscore[hd] = v;
        }
    }
    __syncthreads();

    // Per-head 16-way softmax (LeakyReLU(row+col) scores)
    if (tid < 4) {
        const int hd = tid;
        float ev[16];
        float m = -1e30f;
        #pragma unroll
        for (int k = 0; k < 16; k++) {
            float e = rowscore[hd] + colscore[k][hd];
            e = (e > 0.f) ? e : NEG_SLOPE * e;
            ev[k] = e;
            m = fmaxf(m, e);
        }
        float s = 0.f;
        #pragma unroll
        for (int k = 0; k < 16; k++) { ev[k] = __expf(ev[k] - m); s += ev[k]; }
        float inv = 1.f / s;
        #pragma unroll
        for (int k = 0; k < 16; k++) alpha[k][hd] = ev[k] * inv;
    }
    __syncthreads();

    // Weighted aggregation: thread c owns output feature c (head = c/64)
    const int hd = tid >> 6;
    float acc = 0.f;
    #pragma unroll
    for (int k = 0; k < 16; k++)
        acc += alpha[k][hd] * sh[k][tid];
    out[(size_t)n * OUT_C + tid] = acc;
}

// ---------------------------------------------------------------------------
// Launch. Input order (metadata): row_ptr, col_ind, col_ptr, row_ind,
//                                 feat, W, attn_l, attn_r
// ---------------------------------------------------------------------------
extern "C" void kernel_launch(void* const* d_in, const int* in_sizes, int n_in,
                              void* d_out, int out_size)
{
    const int*   col_ind = (const int*)  d_in[1];
    const float* feat    = (const float*)d_in[4];
    const float* W       = (const float*)d_in[5];
    const float* attn_l  = (const float*)d_in[6];
    const float* attn_r  = (const float*)d_in[7];
    float*       out     = (float*)      d_out;

    const int M = in_sizes[4] / IN_F;   // number of nodes (50000)

    float* h_ptr = nullptr;
    cudaGetSymbolAddress((void**)&h_ptr, g_h);

    dim3 g1((M + 63) / 64, OUT_C / 64);
    gat_gemm_kernel<<<g1, 256>>>(feat, W, h_ptr, M);

    gat_agg_kernel<<<M, 256>>>(col_ind, attn_l, attn_r, out);
}

// round 2
// speedup vs baseline: 2.0770x; 2.0770x over previous
#include <cuda_runtime.h>
#include <cuda_bf16.h>
#include <cstdint>

#define N_NODES   50000
#define DEG       16
#define IN_F      256
#define OUT_C     256   // NUM_HEADS * OUT_FEATS
#define NUM_HEADS 4
#define OUT_F     64
#define NEG_SLOPE 0.2f

typedef unsigned long long ull;

// Scratch: projected features h = feat @ W, [N, 256] fp32 (51.2 MB, L2-resident)
__device__ float g_h [(size_t)N_NODES * OUT_C];
// Per-node attention scores: dot(attn_l, h[n]) and dot(attn_r, h[n]), [N][4]
__device__ float g_sl[(size_t)N_NODES * NUM_HEADS];
__device__ float g_sr[(size_t)N_NODES * NUM_HEADS];

// ---- packed f32x2 helpers (Blackwell FFMA2: ptxas never emits it from C++) ----
__device__ __forceinline__ ull pack2(float x, float y) {
    ull r; asm("mov.b64 %0, {%1, %2};" : "=l"(r) : "f"(x), "f"(y)); return r;
}
__device__ __forceinline__ float2 unpack2(ull v) {
    float2 r; asm("mov.b64 {%0, %1}, %2;" : "=f"(r.x), "=f"(r.y) : "l"(v)); return r;
}
__device__ __forceinline__ ull fma2(ull a, ull b, ull c) {
    ull d; asm("fma.rn.f32x2 %0, %1, %2, %3;" : "=l"(d) : "l"(a), "l"(b), "l"(c)); return d;
}

// ---------------------------------------------------------------------------
// Kernel 1: tiled fp32 GEMM  h[M,256] = feat[M,256] @ W[256,256]
// 64x64 tile, BK=16, 256 threads, 4x4 micro-tile via packed FFMA2.
// Epilogue additionally produces per-node head scores g_sl/g_sr (each block's
// 64 columns are exactly one head, so the head-dot is block-local).
// ---------------------------------------------------------------------------
__global__ __launch_bounds__(256) void gat_gemm_kernel(
    const float* __restrict__ A,     // feat [M,256]
    const float* __restrict__ B,     // W    [256,256]
    float* __restrict__ C,           // g_h  [M,256]
    const float* __restrict__ attn_l,// [256]
    const float* __restrict__ attn_r,// [256]
    int M)
{
    __shared__ float As[16][68];     // pad 4: keeps float4 alignment, breaks conflicts
    __shared__ float Bs[16][64];

    const int bm  = blockIdx.x * 64;
    const int bn  = blockIdx.y * 64;
    const int head = bn >> 6;
    const int tid = threadIdx.x;
    const int tr  = tid >> 4;        // 0..15
    const int tc  = tid & 15;        // 0..15

    ull acc2[4][2];
    #pragma unroll
    for (int i = 0; i < 4; i++) { acc2[i][0] = 0ull; acc2[i][1] = 0ull; }

    for (int k0 = 0; k0 < IN_F; k0 += 16) {
        #pragma unroll
        for (int i = 0; i < 4; i++) {          // A tile 64x16 (transposed store)
            int idx = tid + i * 256;
            int r  = idx >> 4;
            int kk = idx & 15;
            int gr = bm + r;
            As[kk][r] = (gr < M) ? A[(size_t)gr * IN_F + k0 + kk] : 0.f;
        }
        #pragma unroll
        for (int i = 0; i < 4; i++) {          // B tile 16x64
            int idx = tid + i * 256;
            int kk = idx >> 6;
            int c  = idx & 63;
            Bs[kk][c] = B[(size_t)(k0 + kk) * OUT_C + bn + c];
        }
        __syncthreads();

        #pragma unroll
        for (int kk = 0; kk < 16; kk++) {
            float4 av = *reinterpret_cast<const float4*>(&As[kk][tr * 4]);
            ulonglong2 bv = *reinterpret_cast<const ulonglong2*>(&Bs[kk][tc * 4]);
            ull aa0 = pack2(av.x, av.x);
            ull aa1 = pack2(av.y, av.y);
            ull aa2 = pack2(av.z, av.z);
            ull aa3 = pack2(av.w, av.w);
            acc2[0][0] = fma2(aa0, bv.x, acc2[0][0]);
            acc2[0][1] = fma2(aa0, bv.y, acc2[0][1]);
            acc2[1][0] = fma2(aa1, bv.x, acc2[1][0]);
            acc2[1][1] = fma2(aa1, bv.y, acc2[1][1]);
            acc2[2][0] = fma2(aa2, bv.x, acc2[2][0]);
            acc2[2][1] = fma2(aa2, bv.y, acc2[2][1]);
            acc2[3][0] = fma2(aa3, bv.x, acc2[3][0]);
            acc2[3][1] = fma2(aa3, bv.y, acc2[3][1]);
        }
        __syncthreads();
    }

    // attn vector slices for this thread's 4 columns
    float al[4], ar[4];
    #pragma unroll
    for (int j = 0; j < 4; j++) {
        al[j] = attn_l[bn + tc * 4 + j];
        ar[j] = attn_r[bn + tc * 4 + j];
    }

    #pragma unroll
    for (int i = 0; i < 4; i++) {
        int gr = bm + tr * 4 + i;
        float2 c01 = unpack2(acc2[i][0]);
        float2 c23 = unpack2(acc2[i][1]);
        if (gr < M) {
            *reinterpret_cast<float4*>(&C[(size_t)gr * OUT_C + bn + tc * 4]) =
                make_float4(c01.x, c01.y, c23.x, c23.y);
        }
        // per-row partial head dots; reduce across the 16 tc lanes
        float slp = al[0] * c01.x + al[1] * c01.y + al[2] * c23.x + al[3] * c23.y;
        float srp = ar[0] * c01.x + ar[1] * c01.y + ar[2] * c23.x + ar[3] * c23.y;
        #pragma unroll
        for (int off = 1; off < 16; off <<= 1) {
            slp += __shfl_xor_sync(0xffffffff, slp, off);
            srp += __shfl_xor_sync(0xffffffff, srp, off);
        }
        if (tc == 0 && gr < M) {
            g_sl[(size_t)gr * NUM_HEADS + head] = slp;
            g_sr[(size_t)gr * NUM_HEADS + head] = srp;
        }
    }
}

// ---------------------------------------------------------------------------
// Kernel 2: softmax over 16 precomputed edge scores + float4 register
// aggregation. 64 threads per node, 4 nodes per 256-thread block.
// ---------------------------------------------------------------------------
__global__ __launch_bounds__(256) void gat_agg_kernel(
    const int*    __restrict__ col_ind,
    const float4* __restrict__ h4,    // g_h viewed as [N][64] float4
    const float4* __restrict__ sl4,   // g_sl viewed as [N] float4
    const float4* __restrict__ sr4,   // g_sr viewed as [N] float4
    float4*       __restrict__ out4)  // [N][64] float4
{
    const int local = threadIdx.x >> 6;          // node within block (0..3)
    const int t     = threadIdx.x & 63;          // thread within node
    const int n     = blockIdx.x * 4 + local;

    __shared__ int   ssrc  [4][16];
    __shared__ float salpha[4][16][4];

    if (t < 16) {
        int s = col_ind[n * DEG + t];
        ssrc[local][t] = s;

        // edge scores for all 4 heads (LeakyReLU(sl[n] + sr[s]))
        float4 l = sl4[n];
        float4 r = sr4[s];
        float e0 = l.x + r.x, e1 = l.y + r.y, e2 = l.z + r.z, e3 = l.w + r.w;
        e0 = (e0 > 0.f) ? e0 : NEG_SLOPE * e0;
        e1 = (e1 > 0.f) ? e1 : NEG_SLOPE * e1;
        e2 = (e2 > 0.f) ? e2 : NEG_SLOPE * e2;
        e3 = (e3 > 0.f) ? e3 : NEG_SLOPE * e3;

        // 16-lane softmax per head (these 16 threads are lanes 0..15 of a warp)
        float m0 = e0, m1 = e1, m2 = e2, m3 = e3;
        #pragma unroll
        for (int off = 8; off > 0; off >>= 1) {
            m0 = fmaxf(m0, __shfl_xor_sync(0xffffu, m0, off));
            m1 = fmaxf(m1, __shfl_xor_sync(0xffffu, m1, off));
            m2 = fmaxf(m2, __shfl_xor_sync(0xffffu, m2, off));
            m3 = fmaxf(m3, __shfl_xor_sync(0xffffu, m3, off));
        }
        float x0 = __expf(e0 - m0), x1 = __expf(e1 - m1);
        float x2 = __expf(e2 - m2), x3 = __expf(e3 - m3);
        float s0 = x0, s1 = x1, s2 = x2, s3 = x3;
        #pragma unroll
        for (int off = 8; off > 0; off >>= 1) {
            s0 += __shfl_xor_sync(0xffffu, s0, off);
            s1 += __shfl_xor_sync(0xffffu, s1, off);
            s2 += __shfl_xor_sync(0xffffu, s2, off);
            s3 += __shfl_xor_sync(0xffffu, s3, off);
        }
        *reinterpret_cast<float4*>(&salpha[local][t][0]) =
            make_float4(x0 / s0, x1 / s1, x2 / s2, x3 / s3);
    }
    __syncthreads();

    // register aggregation: thread t owns output features 4t..4t+3, head = t/16
    const int hd = t >> 4;
    float4 acc = make_float4(0.f, 0.f, 0.f, 0.f);
    #pragma unroll
    for (int k = 0; k < DEG; k++) {
        float  a = salpha[local][k][hd];
        float4 v = h4[(size_t)ssrc[local][k] * 64 + t];
        acc.x += a * v.x;
        acc.y += a * v.y;
        acc.z += a * v.z;
        acc.w += a * v.w;
    }
    out4[(size_t)n * 64 + t] = acc;
}

// ---------------------------------------------------------------------------
// Launch. Input order: row_ptr, col_ind, col_ptr, row_ind, feat, W, attn_l, attn_r
// ---------------------------------------------------------------------------
extern "C" void kernel_launch(void* const* d_in, const int* in_sizes, int n_in,
                              void* d_out, int out_size)
{
    const int*   col_ind = (const int*)  d_in[1];
    const float* feat    = (const float*)d_in[4];
    const float* W       = (const float*)d_in[5];
    const float* attn_l  = (const float*)d_in[6];
    const float* attn_r  = (const float*)d_in[7];
    float*       out     = (float*)      d_out;

    const int M = in_sizes[4] / IN_F;    // 50000

    float *h_ptr = nullptr, *sl_ptr = nullptr, *sr_ptr = nullptr;
    cudaGetSymbolAddress((void**)&h_ptr,  g_h);
    cudaGetSymbolAddress((void**)&sl_ptr, g_sl);
    cudaGetSymbolAddress((void**)&sr_ptr, g_sr);

    dim3 g1((M + 63) / 64, OUT_C / 64);
    gat_gemm_kernel<<<g1, 256>>>(feat, W, h_ptr, attn_l, attn_r, M);

    gat_agg_kernel<<<M / 4, 256>>>(col_ind,
                                   (const float4*)h_ptr,
                                   (const float4*)sl_ptr,
                                   (const float4*)sr_ptr,
                                   (float4*)out);
}

// round 4
// speedup vs baseline: 3.5329x; 1.7009x over previous
#include <cuda_runtime.h>
#include <cuda_bf16.h>
#include <cstdint>

#define N_NODES   50000
#define N_PAD     50048          // 391 * 128
#define DEG       16
#define IN_F      256
#define OUT_C     256            // NUM_HEADS * OUT_FEATS
#define NUM_HEADS 4
#define OUT_F     64
#define NEG_SLOPE 0.2f

// ---------------- scratch (static device globals; no allocation) ------------
__device__ __nv_bfloat16 g_fhi[(size_t)N_PAD * IN_F];   // feat hi split
__device__ __nv_bfloat16 g_flo[(size_t)N_PAD * IN_F];   // feat lo split
__device__ __nv_bfloat16 g_whi[(size_t)OUT_C * IN_F];   // W^T hi  [n][k]
__device__ __nv_bfloat16 g_wlo[(size_t)OUT_C * IN_F];   // W^T lo
__device__ float g_h [(size_t)N_PAD * OUT_C];           // projected features
__device__ float g_sl[(size_t)N_PAD * NUM_HEADS];       // dst scores
__device__ float g_sr[(size_t)N_PAD * NUM_HEADS];       // src scores

__device__ __forceinline__ uint32_t smem_u32(const void* p) {
    uint32_t a;
    asm("{ .reg .u64 t; cvta.to.shared.u64 t, %1; cvt.u32.u64 %0, t; }" : "=r"(a) : "l"(p));
    return a;
}

__device__ __forceinline__ void ldsm_x4(uint32_t* f, uint32_t addr) {
    asm volatile("ldmatrix.sync.aligned.m8n8.x4.shared.b16 {%0,%1,%2,%3}, [%4];"
                 : "=r"(f[0]), "=r"(f[1]), "=r"(f[2]), "=r"(f[3]) : "r"(addr));
}

__device__ __forceinline__ void mma_bf16(float* c, const uint32_t* a,
                                         uint32_t b0, uint32_t b1) {
    asm volatile("mma.sync.aligned.m16n8k16.row.col.f32.bf16.bf16.f32 "
                 "{%0,%1,%2,%3}, {%4,%5,%6,%7}, {%8,%9}, {%0,%1,%2,%3};"
                 : "+f"(c[0]), "+f"(c[1]), "+f"(c[2]), "+f"(c[3])
                 : "r"(a[0]), "r"(a[1]), "r"(a[2]), "r"(a[3]), "r"(b0), "r"(b1));
}

// ---------------------------------------------------------------------------
// Kernel A: split feat fp32 -> bf16 hi/lo (rows >= M zero-padded)
// ---------------------------------------------------------------------------
__global__ __launch_bounds__(256) void gat_convert_feat(
    const float4* __restrict__ feat4, int M)
{
    const int total = N_PAD * (IN_F / 4);
    for (int i = blockIdx.x * blockDim.x + threadIdx.x; i < total;
         i += gridDim.x * blockDim.x) {
        int row = i >> 6;
        float4 v = (row < M) ? feat4[i] : make_float4(0.f, 0.f, 0.f, 0.f);
        __nv_bfloat16 h0 = __float2bfloat16_rn(v.x);
        __nv_bfloat16 h1 = __float2bfloat16_rn(v.y);
        __nv_bfloat16 h2 = __float2bfloat16_rn(v.z);
        __nv_bfloat16 h3 = __float2bfloat16_rn(v.w);
        __nv_bfloat16 l0 = __float2bfloat16_rn(v.x - __bfloat162float(h0));
        __nv_bfloat16 l1 = __float2bfloat16_rn(v.y - __bfloat162float(h1));
        __nv_bfloat16 l2 = __float2bfloat16_rn(v.z - __bfloat162float(h2));
        __nv_bfloat16 l3 = __float2bfloat16_rn(v.w - __bfloat162float(h3));
        uint2 hv = make_uint2(
            (uint32_t)__bfloat16_as_ushort(h0) | ((uint32_t)__bfloat16_as_ushort(h1) << 16),
            (uint32_t)__bfloat16_as_ushort(h2) | ((uint32_t)__bfloat16_as_ushort(h3) << 16));
        uint2 lv = make_uint2(
            (uint32_t)__bfloat16_as_ushort(l0) | ((uint32_t)__bfloat16_as_ushort(l1) << 16),
            (uint32_t)__bfloat16_as_ushort(l2) | ((uint32_t)__bfloat16_as_ushort(l3) << 16));
        reinterpret_cast<uint2*>(g_fhi)[i] = hv;
        reinterpret_cast<uint2*>(g_flo)[i] = lv;
    }
}

// ---------------------------------------------------------------------------
// Kernel B: transpose-split W [k][n] fp32 -> g_whi/g_wlo [n][k] bf16
// ---------------------------------------------------------------------------
__global__ __launch_bounds__(256) void gat_convert_w(const float* __restrict__ W)
{
    const int n = blockIdx.x;
    for (int k = threadIdx.x; k < IN_F; k += blockDim.x) {
        float x = W[(size_t)k * OUT_C + n];
        __nv_bfloat16 hi = __float2bfloat16_rn(x);
        __nv_bfloat16 lo = __float2bfloat16_rn(x - __bfloat162float(hi));
        g_whi[(size_t)n * IN_F + k] = hi;
        g_wlo[(size_t)n * IN_F + k] = lo;
    }
}

// ---------------------------------------------------------------------------
// Kernel C: mma.sync bf16 GEMM (3-pass split, fp32 accum).
// CTA = 128 rows x 128 cols; 8 warps in 2(m) x 4(n); warp tile 64x32.
// Smem tiles use 80B row stride (32 bf16 + 8 pad): rows hit banks
// {0,20,8,28,16,4,24,12} mod 32 -> conflict-free ldmatrix, no swizzle.
// Epilogue writes g_h and fused per-node attn score dots (no atomics).
// ---------------------------------------------------------------------------
#define TSTR 40   // smem row stride in bf16 elements (80 bytes)

__global__ __launch_bounds__(256) void gat_mma_kernel(
    const float* __restrict__ attn_l,
    const float* __restrict__ attn_r)
{
    __shared__ __align__(16) __nv_bfloat16 sAh[128 * TSTR];
    __shared__ __align__(16) __nv_bfloat16 sAl[128 * TSTR];
    __shared__ __align__(16) __nv_bfloat16 sBh[128 * TSTR];
    __shared__ __align__(16) __nv_bfloat16 sBl[128 * TSTR];
    __shared__ float s_sl[128][2][2];   // [row][head-local][warp-pair]
    __shared__ float s_sr[128][2][2];

    const int tid  = threadIdx.x;
    const int wid  = tid >> 5;
    const int lane = tid & 31;
    const int bm   = blockIdx.x * 128;
    const int bn   = blockIdx.y * 128;
    const int wm   = wid >> 2;          // 0..1
    const int wn   = wid & 3;           // 0..3

    const uint32_t sAh_b = smem_u32(sAh);
    const uint32_t sAl_b = smem_u32(sAl);
    const uint32_t sBh_b = smem_u32(sBh);
    const uint32_t sBl_b = smem_u32(sBl);

    float acc[4][4][4];
    #pragma unroll
    for (int mt = 0; mt < 4; mt++)
        #pragma unroll
        for (int nt = 0; nt < 4; nt++)
            #pragma unroll
            for (int r = 0; r < 4; r++) acc[mt][nt][r] = 0.f;

    // ldmatrix lane-address components
    const int mi  = lane >> 3;                       // matrix id 0..3
    const int aro = ((mi & 1) << 3) + (lane & 7);    // A: row offset within m16
    const int aco = (mi >> 1) << 3;                  // A: k offset (elements)
    const int bro = ((mi >> 1) << 3) + (lane & 7);   // B: n offset within n16
    const int bco = (mi & 1) << 3;                   // B: k offset

    for (int c = 0; c < 8; c++) {                    // k chunks of 32
        __syncthreads();
        #pragma unroll
        for (int i = 0; i < 2; i++) {
            int u   = tid + i * 256;                 // 0..511
            int row = u >> 2, ch = u & 3;
            size_t ga = (size_t)(bm + row) * IN_F + c * 32 + ch * 8;
            size_t gb = (size_t)(bn + row) * IN_F + c * 32 + ch * 8;
            int so = row * TSTR + ch * 8;
            *reinterpret_cast<uint4*>(sAh + so) = *reinterpret_cast<const uint4*>(g_fhi + ga);
            *reinterpret_cast<uint4*>(sAl + so) = *reinterpret_cast<const uint4*>(g_flo + ga);
            *reinterpret_cast<uint4*>(sBh + so) = *reinterpret_cast<const uint4*>(g_whi + gb);
            *reinterpret_cast<uint4*>(sBl + so) = *reinterpret_cast<const uint4*>(g_wlo + gb);
        }
        __syncthreads();

        #pragma unroll
        for (int ks = 0; ks < 2; ks++) {             // two k16 steps
            uint32_t af[4][4];
            uint32_t bh[2][4], bl[2][4];
            #pragma unroll
            for (int bt = 0; bt < 2; bt++) {
                int r = wn * 32 + bt * 16 + bro;
                uint32_t off = (uint32_t)(r * TSTR + ks * 16 + bco) * 2;
                ldsm_x4(bh[bt], sBh_b + off);
                ldsm_x4(bl[bt], sBl_b + off);
            }
            // pass 1+2: A_hi * (B_hi, B_lo)
            #pragma unroll
            for (int mt = 0; mt < 4; mt++) {
                int r = wm * 64 + mt * 16 + aro;
                uint32_t off = (uint32_t)(r * TSTR + ks * 16 + aco) * 2;
                ldsm_x4(af[mt], sAh_b + off);
            }
            #pragma unroll
            for (int mt = 0; mt < 4; mt++)
                #pragma unroll
                for (int nt = 0; nt < 4; nt++) {
                    mma_bf16(acc[mt][nt], af[mt], bh[nt >> 1][(nt & 1) * 2],
                             bh[nt >> 1][(nt & 1) * 2 + 1]);
                    mma_bf16(acc[mt][nt], af[mt], bl[nt >> 1][(nt & 1) * 2],
                             bl[nt >> 1][(nt & 1) * 2 + 1]);
                }
            // pass 3: A_lo * B_hi  (reuse af registers)
            #pragma unroll
            for (int mt = 0; mt < 4; mt++) {
                int r = wm * 64 + mt * 16 + aro;
                uint32_t off = (uint32_t)(r * TSTR + ks * 16 + aco) * 2;
                ldsm_x4(af[mt], sAl_b + off);
            }
            #pragma unroll
            for (int mt = 0; mt < 4; mt++)
                #pragma unroll
                for (int nt = 0; nt < 4; nt++)
                    mma_bf16(acc[mt][nt], af[mt], bh[nt >> 1][(nt & 1) * 2],
                             bh[nt >> 1][(nt & 1) * 2 + 1]);
        }
    }

    // ---- epilogue: store g_h + fused score dots --------------------------
    const int hdl = wn >> 1;             // head-local (0..1) within this CTA
    const int wp  = wn & 1;              // warp pair slot

    // attn slices for this lane's 8 column pairs (4 n-tiles x 2 cols)
    float alv[4][2], arv[4][2];
    #pragma unroll
    for (int nt = 0; nt < 4; nt++) {
        int col = bn + wn * 32 + nt * 8 + (lane & 3) * 2;
        alv[nt][0] = attn_l[col];     alv[nt][1] = attn_l[col + 1];
        arv[nt][0] = attn_r[col];     arv[nt][1] = attn_r[col + 1];
    }

    #pragma unroll
    for (int mt = 0; mt < 4; mt++) {
        int r0 = wm * 64 + mt * 16 + (lane >> 2);
        int r8 = r0 + 8;
        float sl0 = 0.f, sl8 = 0.f, sr0 = 0.f, sr8 = 0.f;
        #pragma unroll
        for (int nt = 0; nt < 4; nt++) {
            int col = bn + wn * 32 + nt * 8 + (lane & 3) * 2;
            float2 v0 = make_float2(acc[mt][nt][0], acc[mt][nt][1]);
            float2 v8 = make_float2(acc[mt][nt][2], acc[mt][nt][3]);
            *reinterpret_cast<float2*>(&g_h[(size_t)(bm + r0) * OUT_C + col]) = v0;
            *reinterpret_cast<float2*>(&g_h[(size_t)(bm + r8) * OUT_C + col]) = v8;
            sl0 += alv[nt][0] * v0.x + alv[nt][1] * v0.y;
            sl8 += alv[nt][0] * v8.x + alv[nt][1] * v8.y;
            sr0 += arv[nt][0] * v0.x + arv[nt][1] * v0.y;
            sr8 += arv[nt][0] * v8.x + arv[nt][1] * v8.y;
        }
        #pragma unroll
        for (int off = 1; off < 4; off <<= 1) {
            sl0 += __shfl_xor_sync(0xffffffffu, sl0, off);
            sl8 += __shfl_xor_sync(0xffffffffu, sl8, off);
            sr0 += __shfl_xor_sync(0xffffffffu, sr0, off);
            sr8 += __shfl_xor_sync(0xffffffffu, sr8, off);
        }
        if ((lane & 3) == 0) {
            s_sl[r0][hdl][wp] = sl0;  s_sl[r8][hdl][wp] = sl8;
            s_sr[r0][hdl][wp] = sr0;  s_sr[r8][hdl][wp] = sr8;
        }
    }
    __syncthreads();

    if (tid < 128) {
        int gr = bm + tid;
        int hb = bn >> 6;   // global head base for this CTA (0 or 2)
        g_sl[(size_t)gr * 4 + hb + 0] = s_sl[tid][0][0] + s_sl[tid][0][1];
        g_sl[(size_t)gr * 4 + hb + 1] = s_sl[tid][1][0] + s_sl[tid][1][1];
        g_sr[(size_t)gr * 4 + hb + 0] = s_sr[tid][0][0] + s_sr[tid][0][1];
        g_sr[(size_t)gr * 4 + hb + 1] = s_sr[tid][1][0] + s_sr[tid][1][1];
    }
}

// ---------------------------------------------------------------------------
// Kernel D: softmax over 16 precomputed edge scores + float4 aggregation.
// 64 threads per node, 4 nodes per block (proven round-2 code).
// ---------------------------------------------------------------------------
__global__ __launch_bounds__(256) void gat_agg_kernel(
    const int*    __restrict__ col_ind,
    const float4* __restrict__ h4,
    const float4* __restrict__ sl4,
    const float4* __restrict__ sr4,
    float4*       __restrict__ out4)
{
    const int local = threadIdx.x >> 6;
    const int t     = threadIdx.x & 63;
    const int n     = blockIdx.x * 4 + local;

    __shared__ int   ssrc  [4][16];
    __shared__ float salpha[4][16][4];

    if (t < 16) {
        int s = col_ind[n * DEG + t];
        ssrc[local][t] = s;
        float4 l = sl4[n];
        float4 r = sr4[s];
        float e0 = l.x + r.x, e1 = l.y + r.y, e2 = l.z + r.z, e3 = l.w + r.w;
        e0 = (e0 > 0.f) ? e0 : NEG_SLOPE * e0;
        e1 = (e1 > 0.f) ? e1 : NEG_SLOPE * e1;
        e2 = (e2 > 0.f) ? e2 : NEG_SLOPE * e2;
        e3 = (e3 > 0.f) ? e3 : NEG_SLOPE * e3;
        float m0 = e0, m1 = e1, m2 = e2, m3 = e3;
        #pragma unroll
        for (int off = 8; off > 0; off >>= 1) {
            m0 = fmaxf(m0, __shfl_xor_sync(0xffffu, m0, off));
            m1 = fmaxf(m1, __shfl_xor_sync(0xffffu, m1, off));
            m2 = fmaxf(m2, __shfl_xor_sync(0xffffu, m2, off));
            m3 = fmaxf(m3, __shfl_xor_sync(0xffffu, m3, off));
        }
        float x0 = __expf(e0 - m0), x1 = __expf(e1 - m1);
        float x2 = __expf(e2 - m2), x3 = __expf(e3 - m3);
        float s0 = x0, s1 = x1, s2 = x2, s3 = x3;
        #pragma unroll
        for (int off = 8; off > 0; off >>= 1) {
            s0 += __shfl_xor_sync(0xffffu, s0, off);
            s1 += __shfl_xor_sync(0xffffu, s1, off);
            s2 += __shfl_xor_sync(0xffffu, s2, off);
            s3 += __shfl_xor_sync(0xffffu, s3, off);
        }
        *reinterpret_cast<float4*>(&salpha[local][t][0]) =
            make_float4(x0 / s0, x1 / s1, x2 / s2, x3 / s3);
    }
    __syncthreads();

    const int hd = t >> 4;
    float4 acc = make_float4(0.f, 0.f, 0.f, 0.f);
    #pragma unroll
    for (int k = 0; k < DEG; k++) {
        float  a = salpha[local][k][hd];
        float4 v = h4[(size_t)ssrc[local][k] * 64 + t];
        acc.x += a * v.x;
        acc.y += a * v.y;
        acc.z += a * v.z;
        acc.w += a * v.w;
    }
    out4[(size_t)n * 64 + t] = acc;
}

// ---------------------------------------------------------------------------
// Launch. Inputs: row_ptr, col_ind, col_ptr, row_ind, feat, W, attn_l, attn_r
// ---------------------------------------------------------------------------
extern "C" void kernel_launch(void* const* d_in, const int* in_sizes, int n_in,
                              void* d_out, int out_size)
{
    const int*   col_ind = (const int*)  d_in[1];
    const float* feat    = (const float*)d_in[4];
    const float* W       = (const float*)d_in[5];
    const float* attn_l  = (const float*)d_in[6];
    const float* attn_r  = (const float*)d_in[7];
    float*       out     = (float*)      d_out;

    const int M = in_sizes[4] / IN_F;    // 50000

    float *h_ptr = nullptr, *sl_ptr = nullptr, *sr_ptr = nullptr;
    cudaGetSymbolAddress((void**)&h_ptr,  g_h);
    cudaGetSymbolAddress((void**)&sl_ptr, g_sl);
    cudaGetSymbolAddress((void**)&sr_ptr, g_sr);

    gat_convert_feat<<<2048, 256>>>((const float4*)feat, M);
    gat_convert_w<<<OUT_C, 256>>>(W);

    dim3 gmm(N_PAD / 128, 2);
    gat_mma_kernel<<<gmm, 256>>>(attn_l, attn_r);

    gat_agg_kernel<<<M / 4, 256>>>(col_ind,
                                   (const float4*)h_ptr,
                                   (const float4*)sl_ptr,
                                   (const float4*)sr_ptr,
                                   (float4*)out);
}